// round 2
// baseline (speedup 1.0000x reference)
#include <cuda_runtime.h>
#include <cuda_bf16.h>
#include <math.h>

// ---------------------------------------------------------------------------
// Problem constants (match reference)
// ---------------------------------------------------------------------------
#define NB      512     // BATCH
#define NA      256     // N_ASSETS
#define CMAX    0.05f   // MAX_WEIGHT
#define NITERS  300     // FISTA iterations
#define NPOW    30      // power iterations
#define NEWT    20      // safeguarded Newton iterations for projection root

// Scratch: symmetric-compressed Q per batch.
//   dRf[b][k][t] : rows 0..127 of Q, full 256 width   (64 MB)
//   dDf[b][k][t] : Q[128+k][128+t], 128x128 block     (32 MB)
__device__ float dRf[(size_t)NB * 128 * 256];
__device__ float dDf[(size_t)NB * 128 * 128];

// ---------------------------------------------------------------------------
// Kernel 1: Q = A^T A  (only the tiles kernel2 needs: (0,0),(0,1),(1,1))
// gridDim = (3, NB), 256 threads, 8x8 microtile per thread, 128x128 CTA tile
// ---------------------------------------------------------------------------
__global__ __launch_bounds__(256) void qgemm_kernel(const float* __restrict__ A) {
    const int tile = blockIdx.x;           // 0:(0,0) 1:(0,128) 2:(128,128)
    const int b    = blockIdx.y;
    const int cj   = (tile == 2) ? 128 : 0;    // row window of Q
    const int ck   = (tile == 0) ? 0   : 128;  // col window of Q

    __shared__ float sA[16][128];
    __shared__ float sB[16][128];

    const int tid = threadIdx.x;
    const int tx  = tid & 15;
    const int ty  = tid >> 4;

    float acc[8][8];
#pragma unroll
    for (int i = 0; i < 8; ++i)
#pragma unroll
        for (int j = 0; j < 8; ++j) acc[i][j] = 0.f;

    const float* __restrict__ Ab = A + (size_t)b * NA * NA;

    for (int ic = 0; ic < NA; ic += 16) {
        // load 16x128 slabs of A (rows ic..ic+15, col windows cj / ck)
#pragma unroll
        for (int u = 0; u < 2; ++u) {
            int idx = tid * 8 + u * 4;          // 0..2047, float4 granules
            int r   = idx >> 7;
            int cc  = idx & 127;
            *(float4*)&sA[r][cc] = *(const float4*)&Ab[(size_t)(ic + r) * NA + cj + cc];
            *(float4*)&sB[r][cc] = *(const float4*)&Ab[(size_t)(ic + r) * NA + ck + cc];
        }
        __syncthreads();

#pragma unroll
        for (int kk = 0; kk < 16; ++kk) {
            float a8[8], b8[8];
            const float4* pa = (const float4*)&sA[kk][ty * 8];
            const float4* pb = (const float4*)&sB[kk][tx * 8];
            float4 a0 = pa[0], a1 = pa[1];
            float4 b0 = pb[0], b1 = pb[1];
            a8[0]=a0.x; a8[1]=a0.y; a8[2]=a0.z; a8[3]=a0.w;
            a8[4]=a1.x; a8[5]=a1.y; a8[6]=a1.z; a8[7]=a1.w;
            b8[0]=b0.x; b8[1]=b0.y; b8[2]=b0.z; b8[3]=b0.w;
            b8[4]=b1.x; b8[5]=b1.y; b8[6]=b1.z; b8[7]=b1.w;
#pragma unroll
            for (int i = 0; i < 8; ++i)
#pragma unroll
                for (int j = 0; j < 8; ++j)
                    acc[i][j] = fmaf(a8[i], b8[j], acc[i][j]);
        }
        __syncthreads();
    }

    // write out
#pragma unroll
    for (int i = 0; i < 8; ++i) {
        int row = ty * 8 + i;              // local row 0..127
        float4 v0 = make_float4(acc[i][0], acc[i][1], acc[i][2], acc[i][3]);
        float4 v1 = make_float4(acc[i][4], acc[i][5], acc[i][6], acc[i][7]);
        if (tile < 2) {
            float* dst = dRf + ((size_t)b * 128 + row) * 256 + ck + tx * 8;
            *(float4*)dst       = v0;
            *(float4*)(dst + 4) = v1;
        } else {
            float* dst = dDf + ((size_t)b * 128 + row) * 128 + tx * 8;
            *(float4*)dst       = v0;
            *(float4*)(dst + 4) = v1;
        }
    }
}

// ---------------------------------------------------------------------------
// Kernel 2: per-batch FISTA. 512 CTAs x 256 threads, Q resident in SMEM.
// SMEM: sR[128*257] (padded rows 0..127 full width) + sD[128*129] + sy + red
// ---------------------------------------------------------------------------
#define SR_ELEMS (128 * 257)
#define SD_ELEMS (128 * 129)
#define SMEM_FLOATS (SR_ELEMS + SD_ELEMS + 256 + 32)
#define SMEM_BYTES (SMEM_FLOATS * 4)

// block-wide reductions; all threads receive bitwise-identical results
__device__ __forceinline__ float2 blk_sum2(float a, float b, float* red, int t) {
#pragma unroll
    for (int o = 16; o > 0; o >>= 1) {
        a += __shfl_xor_sync(0xffffffffu, a, o);
        b += __shfl_xor_sync(0xffffffffu, b, o);
    }
    if ((t & 31) == 0) { red[(t >> 5) * 2] = a; red[(t >> 5) * 2 + 1] = b; }
    __syncthreads();
    float ra = 0.f, rb = 0.f;
#pragma unroll
    for (int i = 0; i < 8; ++i) { ra += red[i * 2]; rb += red[i * 2 + 1]; }
    __syncthreads();
    return make_float2(ra, rb);
}

__device__ __forceinline__ float3 blk_sum3(float a, float b, float c, float* red, int t) {
#pragma unroll
    for (int o = 16; o > 0; o >>= 1) {
        a += __shfl_xor_sync(0xffffffffu, a, o);
        b += __shfl_xor_sync(0xffffffffu, b, o);
        c += __shfl_xor_sync(0xffffffffu, c, o);
    }
    if ((t & 31) == 0) {
        red[(t >> 5) * 3]     = a;
        red[(t >> 5) * 3 + 1] = b;
        red[(t >> 5) * 3 + 2] = c;
    }
    __syncthreads();
    float ra = 0.f, rb = 0.f, rc = 0.f;
#pragma unroll
    for (int i = 0; i < 8; ++i) {
        ra += red[i * 3]; rb += red[i * 3 + 1]; rc += red[i * 3 + 2];
    }
    __syncthreads();
    return make_float3(ra, rb, rc);
}

__device__ __forceinline__ float2 blk_minmax(float v, float* red, int t) {
    float mn = v, mx = v;
#pragma unroll
    for (int o = 16; o > 0; o >>= 1) {
        mn = fminf(mn, __shfl_xor_sync(0xffffffffu, mn, o));
        mx = fmaxf(mx, __shfl_xor_sync(0xffffffffu, mx, o));
    }
    if ((t & 31) == 0) { red[(t >> 5) * 2] = mn; red[(t >> 5) * 2 + 1] = mx; }
    __syncthreads();
    float rm = red[0], rx = red[1];
#pragma unroll
    for (int i = 1; i < 8; ++i) {
        rm = fminf(rm, red[i * 2]);
        rx = fmaxf(rx, red[i * 2 + 1]);
    }
    __syncthreads();
    return make_float2(rm, rx);
}

// g_t = sum_k Q[k][t] * y[k]  (Q symmetric; compressed storage)
__device__ __forceinline__ float matvec256(const float* __restrict__ sR,
                                           const float* __restrict__ sD,
                                           const float* __restrict__ sy,
                                           int t) {
    float g = 0.f;
    const float4* __restrict__ y4 = (const float4*)sy;
    // k = 0..127: Q[k][t] = R[k][t] (contiguous across lanes)
#pragma unroll
    for (int k4 = 0; k4 < 32; ++k4) {
        const float4 yv = y4[k4];
        const int k = k4 * 4;
        g = fmaf(sR[(k + 0) * 257 + t], yv.x, g);
        g = fmaf(sR[(k + 1) * 257 + t], yv.y, g);
        g = fmaf(sR[(k + 2) * 257 + t], yv.z, g);
        g = fmaf(sR[(k + 3) * 257 + t], yv.w, g);
    }
    if (t < 128) {
        // k = 128..255: Q[k][t] = R[t][k] (stride-257 reads, banks (t+k)%32 distinct)
        const float* __restrict__ rp = sR + t * 257;
#pragma unroll
        for (int k4 = 32; k4 < 64; ++k4) {
            const float4 yv = y4[k4];
            const int k = k4 * 4;
            g = fmaf(rp[k + 0], yv.x, g);
            g = fmaf(rp[k + 1], yv.y, g);
            g = fmaf(rp[k + 2], yv.z, g);
            g = fmaf(rp[k + 3], yv.w, g);
        }
    } else {
        // k = 128..255: Q[k][t] = D[k-128][t-128] (contiguous across lanes)
        const float* __restrict__ dp = sD + (t - 128);
#pragma unroll
        for (int k4 = 32; k4 < 64; ++k4) {
            const float4 yv = y4[k4];
            const int kl = k4 * 4 - 128;
            g = fmaf(dp[(kl + 0) * 129], yv.x, g);
            g = fmaf(dp[(kl + 1) * 129], yv.y, g);
            g = fmaf(dp[(kl + 2) * 129], yv.z, g);
            g = fmaf(dp[(kl + 3) * 129], yv.w, g);
        }
    }
    return g;
}

// Projection of v (one coord per thread) onto {sum=1, |w|<=c}.
// Safeguarded Newton on s(tau) = sum clip(v - tau), then the reference's exact
// active-set recompute of tau (piecewise-exact, matches ref's 60-step bisection).
__device__ __forceinline__ float project_capped(float v, int t, float* red) {
    float2 mm = blk_minmax(v, red, t);
    float lo = mm.x - CMAX;
    float hi = mm.y + CMAX;
    float tau = 0.5f * (lo + hi);

#pragma unroll 1
    for (int it = 0; it < NEWT; ++it) {
        float z   = v - tau;
        float zc  = fminf(fmaxf(z, -CMAX), CMAX);
        float inr = (fabsf(z) < CMAX) ? 1.f : 0.f;
        float2 sc = blk_sum2(zc, inr, red, t);
        if (sc.x > 1.f) lo = tau; else hi = tau;
        float tn;
        if (sc.y >= 1.f) tn = tau + (sc.x - 1.f) / sc.y;
        else             tn = 0.5f * (lo + hi);
        if (!(tn > lo && tn < hi)) tn = 0.5f * (lo + hi);
        tau = tn;
    }

    // exact tau from the active set at tau (same formula as reference)
    float z   = v - tau;
    float inr = (fabsf(z) < CMAX) ? 1.f : 0.f;
    float khd = ((z >= CMAX) ? 1.f : 0.f) - ((z <= -CMAX) ? 1.f : 0.f);
    float3 r3 = blk_sum3(inr * v, khd, inr, red, t);
    float denom = fmaxf(r3.z, 1.f);
    float tau2  = (r3.x + CMAX * r3.y - 1.f) / denom;
    return fminf(fmaxf(v - tau2, -CMAX), CMAX);
}

__global__ __launch_bounds__(256) void fista_kernel(float* __restrict__ out) {
    extern __shared__ float sm[];
    float* sR  = sm;
    float* sD  = sm + SR_ELEMS;
    float* sy  = sD + SD_ELEMS;
    float* red = sy + 256;

    const int b = blockIdx.x;
    const int t = threadIdx.x;

    // --- load compressed Q into SMEM (padded) ---
    {
        const float* __restrict__ gR = dRf + (size_t)b * 128 * 256;
        for (int i = t; i < 128 * 256; i += 256) {
            int r = i >> 8, c = i & 255;
            sR[r * 257 + c] = gR[i];
        }
        const float* __restrict__ gD = dDf + (size_t)b * 128 * 128;
        for (int i = t; i < 128 * 128; i += 256) {
            int r = i >> 7, c = i & 127;
            sD[r * 129 + c] = gD[i];
        }
    }
    sy[t] = 1.f / 16.f;   // u0 = 1/sqrt(256)
    __syncthreads();

    // --- power iteration for lambda_max ---
    for (int pi = 0; pi < NPOW; ++pi) {
        float g = matvec256(sR, sD, sy, t);
        float2 nr = blk_sum2(g * g, 0.f, red, t);
        float inv = 1.f / (sqrtf(nr.x) + 1e-12f);
        sy[t] = g * inv;
        __syncthreads();
    }
    float lmax;
    {
        float g = matvec256(sR, sD, sy, t);
        float2 d = blk_sum2(sy[t] * g, 0.f, red, t);
        lmax = d.x;
    }
    const float s2 = 2.f / (2.f * lmax + 1e-12f);   // step * 2

    // --- FISTA ---
    float w  = 1.f / 256.f;   // w0 = proj(uniform) = uniform (exact)
    float tk = 1.f;
    sy[t] = w;
    __syncthreads();

#pragma unroll 1
    for (int it = 0; it < NITERS; ++it) {
        float g  = matvec256(sR, sD, sy, t);
        float yv = sy[t];
        float v  = yv - s2 * g;                 // y - step * (2 Q y)
        float wn = project_capped(v, t, red);   // contains syncthreads
        float tn = 0.5f * (1.f + sqrtf(1.f + 4.f * tk * tk));
        float coef = (tk - 1.f) / tn;
        float yn = wn + coef * (wn - w);
        w  = wn;
        tk = tn;
        sy[t] = yn;
        __syncthreads();
    }

    out[(size_t)b * 256 + t] = w;
}

// ---------------------------------------------------------------------------
extern "C" void kernel_launch(void* const* d_in, const int* in_sizes, int n_in,
                              void* d_out, int out_size) {
    const float* A = (const float*)d_in[0];
    float* out = (float*)d_out;

    cudaFuncSetAttribute(fista_kernel,
                         cudaFuncAttributeMaxDynamicSharedMemorySize, SMEM_BYTES);

    qgemm_kernel<<<dim3(3, NB), 256>>>(A);
    fista_kernel<<<NB, 256, SMEM_BYTES>>>(out);
}

// round 3
// speedup vs baseline: 1.0653x; 1.0653x over previous
#include <cuda_runtime.h>
#include <cuda_bf16.h>
#include <math.h>

// ---------------------------------------------------------------------------
// Problem constants (match reference)
// ---------------------------------------------------------------------------
#define NB      512     // BATCH
#define NA      256     // N_ASSETS
#define CMAX    0.05f   // MAX_WEIGHT
#define NITERS  300     // FISTA iterations
#define NPOW    30      // power iterations
#define NEWT    20      // safeguarded Newton iterations for projection root

// Scratch: symmetric-compressed Q per batch (compact in GMEM, padded in SMEM).
__device__ float dRf[(size_t)NB * 128 * 256];   // rows 0..127 of Q, full width
__device__ float dDf[(size_t)NB * 128 * 128];   // Q[128+i][128+j]

// ---------------------------------------------------------------------------
// Kernel 1: Q = A^T A  (tiles (0,0),(0,1),(1,1) only; Q symmetric)
// ---------------------------------------------------------------------------
__global__ __launch_bounds__(256) void qgemm_kernel(const float* __restrict__ A) {
    const int tile = blockIdx.x;               // 0:(0,0) 1:(0,128) 2:(128,128)
    const int b    = blockIdx.y;
    const int cj   = (tile == 2) ? 128 : 0;    // row window of Q
    const int ck   = (tile == 0) ? 0   : 128;  // col window of Q

    __shared__ float sA[16][128];
    __shared__ float sB[16][128];

    const int tid = threadIdx.x;
    const int tx  = tid & 15;
    const int ty  = tid >> 4;

    float acc[8][8];
#pragma unroll
    for (int i = 0; i < 8; ++i)
#pragma unroll
        for (int j = 0; j < 8; ++j) acc[i][j] = 0.f;

    const float* __restrict__ Ab = A + (size_t)b * NA * NA;

    for (int ic = 0; ic < NA; ic += 16) {
#pragma unroll
        for (int u = 0; u < 2; ++u) {
            int idx = tid * 8 + u * 4;
            int r   = idx >> 7;
            int cc  = idx & 127;
            *(float4*)&sA[r][cc] = *(const float4*)&Ab[(size_t)(ic + r) * NA + cj + cc];
            *(float4*)&sB[r][cc] = *(const float4*)&Ab[(size_t)(ic + r) * NA + ck + cc];
        }
        __syncthreads();

#pragma unroll
        for (int kk = 0; kk < 16; ++kk) {
            float a8[8], b8[8];
            const float4* pa = (const float4*)&sA[kk][ty * 8];
            const float4* pb = (const float4*)&sB[kk][tx * 8];
            float4 a0 = pa[0], a1 = pa[1];
            float4 b0 = pb[0], b1 = pb[1];
            a8[0]=a0.x; a8[1]=a0.y; a8[2]=a0.z; a8[3]=a0.w;
            a8[4]=a1.x; a8[5]=a1.y; a8[6]=a1.z; a8[7]=a1.w;
            b8[0]=b0.x; b8[1]=b0.y; b8[2]=b0.z; b8[3]=b0.w;
            b8[4]=b1.x; b8[5]=b1.y; b8[6]=b1.z; b8[7]=b1.w;
#pragma unroll
            for (int i = 0; i < 8; ++i)
#pragma unroll
                for (int j = 0; j < 8; ++j)
                    acc[i][j] = fmaf(a8[i], b8[j], acc[i][j]);
        }
        __syncthreads();
    }

#pragma unroll
    for (int i = 0; i < 8; ++i) {
        int row = ty * 8 + i;
        float4 v0 = make_float4(acc[i][0], acc[i][1], acc[i][2], acc[i][3]);
        float4 v1 = make_float4(acc[i][4], acc[i][5], acc[i][6], acc[i][7]);
        if (tile < 2) {
            float* dst = dRf + ((size_t)b * 128 + row) * 256 + ck + tx * 8;
            *(float4*)dst       = v0;
            *(float4*)(dst + 4) = v1;
        } else {
            float* dst = dDf + ((size_t)b * 128 + row) * 128 + tx * 8;
            *(float4*)dst       = v0;
            *(float4*)(dst + 4) = v1;
        }
    }
}

// ---------------------------------------------------------------------------
// Kernel 2: per-batch FISTA, Q resident in SMEM, warp-replicated projection.
// SMEM: sR[128 x 260] (pitch 65 float4, odd -> conflict-free row reads)
//       sD[128 x 132] (pitch 33 float4, odd)
// ---------------------------------------------------------------------------
#define RP 260
#define DP 132
#define SR_ELEMS (128 * RP)
#define SD_ELEMS (128 * DP)
#define SMEM_FLOATS (SR_ELEMS + SD_ELEMS + 256 + 256 + 64)
#define SMEM_BYTES (SMEM_FLOATS * 4)

// block reduction (power-iteration phase only)
__device__ __forceinline__ float blk_sum(float a, float* red, int t) {
#pragma unroll
    for (int o = 16; o > 0; o >>= 1)
        a += __shfl_xor_sync(0xffffffffu, a, o);
    if ((t & 31) == 0) red[t >> 5] = a;
    __syncthreads();
    float r = 0.f;
#pragma unroll
    for (int i = 0; i < 8; ++i) r += red[i];
    __syncthreads();
    return r;
}

// g_t = sum_k Q[k][t] * y[k]  (symmetric-compressed, float4 where contiguous)
__device__ __forceinline__ float matvec256(const float* __restrict__ sR,
                                           const float* __restrict__ sD,
                                           const float* __restrict__ sy,
                                           int t) {
    float g = 0.f;
    const float4* __restrict__ y4 = (const float4*)sy;
    if (t < 128) {
        // row t of Q (== column t by symmetry), fully contiguous
        const float4* __restrict__ qr = (const float4*)(sR + t * RP);
#pragma unroll
        for (int k = 0; k < 64; ++k) {
            float4 q = qr[k], y = y4[k];
            g = fmaf(q.x, y.x, g); g = fmaf(q.y, y.y, g);
            g = fmaf(q.z, y.z, g); g = fmaf(q.w, y.w, g);
        }
    } else {
        // k = 0..127: column t of R (stride RP; banks (4k+t)%32 distinct)
        const float* __restrict__ qc = sR + t;
#pragma unroll
        for (int k4 = 0; k4 < 32; ++k4) {
            float4 y = y4[k4];
            const int k = k4 * 4;
            g = fmaf(qc[(k + 0) * RP], y.x, g);
            g = fmaf(qc[(k + 1) * RP], y.y, g);
            g = fmaf(qc[(k + 2) * RP], y.z, g);
            g = fmaf(qc[(k + 3) * RP], y.w, g);
        }
        // k = 128..255: row (t-128) of D (D symmetric), contiguous
        const float4* __restrict__ dr = (const float4*)(sD + (t - 128) * DP);
#pragma unroll
        for (int k = 0; k < 32; ++k) {
            float4 q = dr[k], y = y4[k + 32];
            g = fmaf(q.x, y.x, g); g = fmaf(q.y, y.y, g);
            g = fmaf(q.z, y.z, g); g = fmaf(q.w, y.w, g);
        }
    }
    return g;
}

__global__ __launch_bounds__(256) void fista_kernel(float* __restrict__ out) {
    extern __shared__ float sm[];
    float* sR  = sm;
    float* sD  = sm + SR_ELEMS;
    float* sy  = sD + SD_ELEMS;
    float* sv  = sy + 256;
    float* red = sv + 256;

    const int b    = blockIdx.x;
    const int t    = threadIdx.x;
    const int lane = t & 31;
    const int wid  = t >> 5;

    // --- load compressed Q into padded SMEM (float4 granularity) ---
    {
        const float4* __restrict__ gR = (const float4*)(dRf + (size_t)b * 128 * 256);
        float4* sR4 = (float4*)sR;
        for (int i = t; i < 128 * 64; i += 256) {
            int r = i >> 6, c = i & 63;
            sR4[r * 65 + c] = gR[i];
        }
        const float4* __restrict__ gD = (const float4*)(dDf + (size_t)b * 128 * 128);
        float4* sD4 = (float4*)sD;
        for (int i = t; i < 128 * 32; i += 256) {
            int r = i >> 5, c = i & 31;
            sD4[r * 33 + c] = gD[i];
        }
    }
    sy[t] = 0.0625f;   // 1/sqrt(256)
    __syncthreads();

    // --- power iteration for lambda_max (block reductions: cheap, 30 iters) ---
    for (int pi = 0; pi < NPOW; ++pi) {
        float g = matvec256(sR, sD, sy, t);
        float nr = blk_sum(g * g, red, t);
        sy[t] = g * (1.f / (sqrtf(nr) + 1e-12f));
        __syncthreads();
    }
    float s2;
    {
        float g = matvec256(sR, sD, sy, t);
        float lmax = blk_sum(sy[t] * g, red, t);
        s2 = 2.f / (2.f * lmax + 1e-12f);   // step * 2
    }

    // --- FISTA (warp-replicated projection: no barriers inside Newton) ---
    float w_loc[8];
#pragma unroll
    for (int j = 0; j < 8; ++j) w_loc[j] = 1.f / 256.f;  // proj(uniform)=uniform
    float tk = 1.f;
    sy[t] = 1.f / 256.f;
    __syncthreads();

#pragma unroll 1
    for (int it = 0; it < NITERS; ++it) {
        float g = matvec256(sR, sD, sy, t);
        sv[t] = sy[t] - s2 * g;             // v = y - step * (2 Q y)
        __syncthreads();

        // every warp loads the full v (8 coords/lane, bank = lane: conflict-free)
        float v[8];
#pragma unroll
        for (int j = 0; j < 8; ++j) v[j] = sv[lane + 32 * j];

        // bracket via warp min/max
        float mn = v[0], mx = v[0];
#pragma unroll
        for (int j = 1; j < 8; ++j) { mn = fminf(mn, v[j]); mx = fmaxf(mx, v[j]); }
#pragma unroll
        for (int o = 16; o > 0; o >>= 1) {
            mn = fminf(mn, __shfl_xor_sync(0xffffffffu, mn, o));
            mx = fmaxf(mx, __shfl_xor_sync(0xffffffffu, mx, o));
        }
        float lo = mn - CMAX, hi = mx + CMAX;
        float tau = 0.5f * (lo + hi);

        // safeguarded Newton on s(tau) = sum clip(v - tau, -c, c) - 1
#pragma unroll 1
        for (int nit = 0; nit < NEWT; ++nit) {
            float s = 0.f, cn = 0.f;
#pragma unroll
            for (int j = 0; j < 8; ++j) {
                float z = v[j] - tau;
                s  += fminf(fmaxf(z, -CMAX), CMAX);
                cn += (fabsf(z) < CMAX) ? 1.f : 0.f;
            }
#pragma unroll
            for (int o = 16; o > 0; o >>= 1) {
                s  += __shfl_xor_sync(0xffffffffu, s,  o);
                cn += __shfl_xor_sync(0xffffffffu, cn, o);
            }
            if (s > 1.f) lo = tau; else hi = tau;
            float tn = (cn >= 1.f) ? tau + (s - 1.f) / cn : 0.5f * (lo + hi);
            if (!(tn > lo && tn < hi)) tn = 0.5f * (lo + hi);
            tau = tn;
        }

        // exact tau from the active set (reference's recompute formula)
        float sa = 0.f, sk = 0.f, si = 0.f;
#pragma unroll
        for (int j = 0; j < 8; ++j) {
            float z   = v[j] - tau;
            float inr = (fabsf(z) < CMAX) ? 1.f : 0.f;
            sa += inr * v[j];
            sk += ((z >= CMAX) ? 1.f : 0.f) - ((z <= -CMAX) ? 1.f : 0.f);
            si += inr;
        }
#pragma unroll
        for (int o = 16; o > 0; o >>= 1) {
            sa += __shfl_xor_sync(0xffffffffu, sa, o);
            sk += __shfl_xor_sync(0xffffffffu, sk, o);
            si += __shfl_xor_sync(0xffffffffu, si, o);
        }
        float tau2 = (sa + CMAX * sk - 1.f) / fmaxf(si, 1.f);

        // FISTA momentum (scalar, identical in all threads)
        float tn   = 0.5f * (1.f + sqrtf(1.f + 4.f * tk * tk));
        float coef = (tk - 1.f) / tn;
        tk = tn;

        float yn_own = 0.f;
#pragma unroll
        for (int j = 0; j < 8; ++j) {
            float wn = fminf(fmaxf(v[j] - tau2, -CMAX), CMAX);
            float yn = wn + coef * (wn - w_loc[j]);
            w_loc[j] = wn;
            if (j == wid) yn_own = yn;   // warp `wid` owns coord slice j==wid
        }
        sy[lane + 32 * wid] = yn_own;    // disjoint writes, identical values
        __syncthreads();
    }

    // output: warp wid writes coords lane + 32*wid
    float w_own = w_loc[0];
#pragma unroll
    for (int j = 1; j < 8; ++j) if (j == wid) w_own = w_loc[j];
    out[(size_t)b * 256 + lane + 32 * wid] = w_own;
}

// ---------------------------------------------------------------------------
extern "C" void kernel_launch(void* const* d_in, const int* in_sizes, int n_in,
                              void* d_out, int out_size) {
    const float* A = (const float*)d_in[0];
    float* out = (float*)d_out;

    cudaFuncSetAttribute(fista_kernel,
                         cudaFuncAttributeMaxDynamicSharedMemorySize, SMEM_BYTES);

    qgemm_kernel<<<dim3(3, NB), 256>>>(A);
    fista_kernel<<<NB, 256, SMEM_BYTES>>>(out);
}